// round 8
// baseline (speedup 1.0000x reference)
#include <cuda_runtime.h>
#include <cuda_fp16.h>
#include <mma.h>
#include <math.h>

using namespace nvcuda;

#define NNODES 20000
#define NEDGES 200000
#define NC     32
#define FDIM   13
#define FHID   64
#define NREP   10
#define OUTC   (NC * (NREP + 1))   // 352
#define MPAD   20032               // NNODES padded to 64

// Scratch (__device__ globals; allocation-free rule)
__device__ __half g_Q[(size_t)MPAD * 2048];       // 82 MB per-node projections
__device__ __half g_h1[(size_t)NEDGES * FHID];    // 25.6 MB (edge order)
__device__ __half g_fW2pp[32 * 2048];             // permuted fW2: [i][o*64+k]
__device__ __half g_hxh[(size_t)MPAD * NC];       // fp16 copy of current hx
__device__ float  g_msg[(size_t)NEDGES * NC];     // 25.6 MB msgs, dst-sorted
__device__ float  g_deg[NNODES];
__device__ int    g_cnt[NNODES], g_cur[NNODES];   // src CSR build
__device__ int    g_cntd[NNODES], g_curd[NNODES]; // dst CSR build
__device__ int    g_off[NNODES + 1];              // src CSR offsets
__device__ int    g_offd[NNODES + 1];             // dst CSR offsets
__device__ int    g_perm[NEDGES];                 // src-sorted pos -> edge id
__device__ int    g_dpos[NEDGES];                 // src-sorted pos -> dst-sorted pos

typedef unsigned long long ull;

__device__ __forceinline__ float2 int_as_f2h(int v) {
    __half2 h; *(int*)&h = v; return __half22float2(h);
}
__device__ __forceinline__ ull pack2(float x, float y) {
    ull r; asm("mov.b64 %0, {%1, %2};" : "=l"(r) : "f"(x), "f"(y)); return r;
}
__device__ __forceinline__ ull fma2(ull a, ull b, ull c) {
    ull d; asm("fma.rn.f32x2 %0, %1, %2, %3;" : "=l"(d) : "l"(a), "l"(b), "l"(c)); return d;
}
__device__ __forceinline__ float sum2(ull v) {
    float x, y; asm("mov.b64 {%0, %1}, %2;" : "=f"(x), "=f"(y) : "l"(v)); return x + y;
}

// ---------------------------------------------------------------------------
// prep0: h1 (warp/edge) + zero counters + copy0 + fW2 permute
// ---------------------------------------------------------------------------
__global__ void prep0_kernel(const float* __restrict__ ef,
                             const float* __restrict__ fW1,
                             const float* __restrict__ fb1,
                             const float* __restrict__ fW2,
                             const float* __restrict__ hx,
                             float* __restrict__ out,
                             int N, int E) {
    int gtid = blockIdx.x * blockDim.x + threadIdx.x;
    int e    = gtid >> 5;
    int lane = gtid & 31;

    if (e < E) {
        float efv = (lane < FDIM) ? ef[(size_t)e * FDIM + lane] : 0.f;
        float a0 = fb1[lane], a1 = fb1[lane + 32];
#pragma unroll
        for (int j = 0; j < FDIM; j++) {
            float x = __shfl_sync(0xffffffffu, efv, j);
            a0 = fmaf(x, fW1[j * FHID + lane],      a0);
            a1 = fmaf(x, fW1[j * FHID + lane + 32], a1);
        }
        g_h1[(size_t)e * FHID + lane]      = __float2half_rn(fmaxf(a0, 0.f));
        g_h1[(size_t)e * FHID + lane + 32] = __float2half_rn(fmaxf(a1, 0.f));
    }
    if (gtid < N * NC) {
        float v = hx[gtid];
        out[(size_t)(gtid >> 5) * OUTC + (gtid & 31)] = v;
        g_hxh[gtid] = __float2half_rn(v);
    }
    if (gtid < N) {
        g_cnt[gtid] = 0; g_cur[gtid] = 0;
        g_cntd[gtid] = 0; g_curd[gtid] = 0;
    }
    if (gtid < (MPAD - NNODES) * NC)
        g_hxh[(size_t)NNODES * NC + gtid] = __float2half_rn(0.f);
    if (gtid < 32 * 2048) {
        int i = gtid >> 11, rem = gtid & 2047, o = rem >> 6, k = rem & 63;
        g_fW2pp[gtid] = __float2half_rn(fW2[k * 1024 + i * 32 + o]);
    }
}

__global__ void count_kernel(const int* __restrict__ src,
                             const int* __restrict__ dst, int E) {
    int e = blockIdx.x * blockDim.x + threadIdx.x;
    if (e >= E) return;
    atomicAdd(&g_cnt[src[e]], 1);
    atomicAdd(&g_cntd[dst[e]], 1);
}

// exclusive scans: g_cnt->g_off and g_cntd->g_offd (single block)
__global__ void scan_kernel(int N) {
    __shared__ int part[256];
    int t = threadIdx.x;
    int chunk = (N + 255) / 256;
    int lo = t * chunk, hi = min(lo + chunk, N);

    int s = 0;
    for (int i = lo; i < hi; i++) s += g_cnt[i];
    part[t] = s;
    __syncthreads();
    if (t == 0) {
        int run = 0;
        for (int i = 0; i < 256; i++) { int v = part[i]; part[i] = run; run += v; }
        g_off[N] = run;
    }
    __syncthreads();
    int run = part[t];
    for (int i = lo; i < hi; i++) { g_off[i] = run; run += g_cnt[i]; }
    __syncthreads();

    s = 0;
    for (int i = lo; i < hi; i++) s += g_cntd[i];
    part[t] = s;
    __syncthreads();
    if (t == 0) {
        int run2 = 0;
        for (int i = 0; i < 256; i++) { int v = part[i]; part[i] = run2; run2 += v; }
        g_offd[N] = run2;
    }
    __syncthreads();
    run = part[t];
    for (int i = lo; i < hi; i++) { g_offd[i] = run; run += g_cntd[i]; }
}

// CSR scatter (both orders) + invdeg
__global__ void scatter_kernel(const int* __restrict__ src,
                               const int* __restrict__ dst, int N, int E) {
    int e = blockIdx.x * blockDim.x + threadIdx.x;
    if (e < E) {
        int s = src[e], d = dst[e];
        int ps = g_off[s]  + atomicAdd(&g_cur[s], 1);
        int pd = g_offd[d] + atomicAdd(&g_curd[d], 1);
        g_perm[ps] = e;
        g_dpos[ps] = pd;
    }
    if (e < N) g_deg[e] = 1.0f / fmaxf((float)g_cntd[e], 1.0f);
}

// ---------------------------------------------------------------------------
// Q = hxh @ fW2pp : WMMA, block tile 64(M) x 128(N), K=32.
// A loaded straight from global; acc converted to fp16 in regs and stored
// straight to global. Only B passes through smem (8KB, loaded once).
// ---------------------------------------------------------------------------
#define QBS_LD 136

__global__ void qgemm_kernel() {
    __shared__ __align__(16) __half Bs[32 * QBS_LD];

    const int m0 = blockIdx.x * 64;
    const int n0 = blockIdx.y * 128;
    const int tid = threadIdx.x;
    const int wid = tid >> 5;
    const int wm = wid & 3, wn = wid >> 2;

#pragma unroll
    for (int i = tid; i < 512; i += 256) {
        int r = i >> 4, s = i & 15;
        *(int4*)(Bs + r * QBS_LD + s * 8) =
            *(const int4*)(g_fW2pp + (size_t)r * 2048 + n0 + s * 8);
    }
    __syncthreads();

    wmma::fragment<wmma::accumulator, 16, 16, 16, float> acc[4];
#pragma unroll
    for (int j = 0; j < 4; j++) wmma::fill_fragment(acc[j], 0.0f);

#pragma unroll
    for (int k = 0; k < 2; k++) {
        wmma::fragment<wmma::matrix_a, 16, 16, 16, __half, wmma::row_major> af;
        wmma::load_matrix_sync(af, g_hxh + (size_t)(m0 + wm * 16) * NC + k * 16, NC);
#pragma unroll
        for (int j = 0; j < 4; j++) {
            wmma::fragment<wmma::matrix_b, 16, 16, 16, __half, wmma::row_major> bf;
            wmma::load_matrix_sync(bf, Bs + (k * 16) * QBS_LD + wn * 64 + j * 16, QBS_LD);
            wmma::mma_sync(acc[j], af, bf, acc[j]);
        }
    }

    // convert in registers, store fp16 fragments straight to global
#pragma unroll
    for (int j = 0; j < 4; j++) {
        wmma::fragment<wmma::accumulator, 16, 16, 16, __half> hc;
#pragma unroll
        for (int i = 0; i < hc.num_elements; i++)
            hc.x[i] = __float2half_rn(acc[j].x[i]);
        wmma::store_matrix_sync(g_Q + (size_t)(m0 + wm * 16) * 2048 + n0 + wn * 64 + j * 16,
                                hc, 2048, wmma::mem_row_major);
    }
}

// ---------------------------------------------------------------------------
// msg: warp per src node; smem broadcast of h1, f32x2 FMA with 4 independent
// accumulators (chain depth 8), store to dst-sorted g_msg (no atomics).
// ---------------------------------------------------------------------------
#define MSG_WARPS 8
__global__ void msg_kernel(const float* __restrict__ out,
                           const float* __restrict__ fb2,
                           int N, int t) {
    __shared__ __align__(16) ull hbuf[MSG_WARPS][2][32];
    int n    = (blockIdx.x * blockDim.x + threadIdx.x) >> 5;
    int lane = threadIdx.x & 31;
    int w    = (threadIdx.x >> 5);
    if (n >= N) return;
    int start = __ldg(&g_off[n]), end = __ldg(&g_off[n + 1]);
    if (start == end) return;

    // Q row -> packed f32x2 registers (lane o owns k=0..63 -> 32 pairs)
    ull qf2[32];
    const int4* qp = (const int4*)(g_Q + (size_t)n * 2048 + lane * 64);
#pragma unroll
    for (int j = 0; j < 8; j++) {
        int4 v = __ldg(qp + j);
        const int* vi = (const int*)&v;
#pragma unroll
        for (int u = 0; u < 4; u++) {
            float2 f = int_as_f2h(vi[u]);
            qf2[j * 4 + u] = pack2(f.x, f.y);
        }
    }
    // bias: bn[o] = sum_i hx[n,i] * fb2[i*32+o]
    float hxl = out[(size_t)n * OUTC + (size_t)(t - 1) * NC + lane];
    float bn = 0.f;
#pragma unroll
    for (int i = 0; i < NC; i++)
        bn = fmaf(__shfl_sync(0xffffffffu, hxl, i), fb2[i * 32 + lane], bn);

    const int* h1i = (const int*)g_h1;

    // prefetch first edge
    int p = start;
    int e0 = __ldg(&g_perm[p]);
    int dp0 = __ldg(&g_dpos[p]);
    int hv0 = __ldg(h1i + (size_t)e0 * 32 + lane);

    while (p < end) {
        int hv = hv0, dp = dp0;
        int np = p + 1;
        if (np < end) {                        // prefetch next (overlaps compute)
            int e1 = __ldg(&g_perm[np]);
            dp0 = __ldg(&g_dpos[np]);
            hv0 = __ldg(h1i + (size_t)e1 * 32 + lane);
        }
        int buf = p & 1;
        ull* hb = &hbuf[w][buf][0];

        float2 hf = int_as_f2h(hv);
        hb[lane] = pack2(hf.x, hf.y);          // h[2*lane], h[2*lane+1]
        __syncwarp();

        ull a0 = 0, a1 = 0, a2 = 0, a3 = 0;    // 4 independent chains
#pragma unroll
        for (int j = 0; j < 32; j += 4) {
            a0 = fma2(hb[j],     qf2[j],     a0);
            a1 = fma2(hb[j + 1], qf2[j + 1], a1);
            a2 = fma2(hb[j + 2], qf2[j + 2], a2);
            a3 = fma2(hb[j + 3], qf2[j + 3], a3);
        }
        float m = (sum2(a0) + sum2(a1)) + (sum2(a2) + sum2(a3));
        g_msg[(size_t)dp * NC + lane] = m + bn;
        p = np;
    }
}

// ---------------------------------------------------------------------------
// GRU: warp per node. Segmented sum over dst-CSR msgs, then GRU math.
// ---------------------------------------------------------------------------
__global__ void gru_kernel(float* __restrict__ out,
                           const float* __restrict__ Wi,
                           const float* __restrict__ Wh,
                           const float* __restrict__ bi,
                           const float* __restrict__ bh,
                           int N, int t) {
    int n    = (blockIdx.x * blockDim.x + threadIdx.x) >> 5;
    int lane = threadIdx.x & 31;
    if (n >= N) return;

    int s = __ldg(&g_offd[n]), e = __ldg(&g_offd[n + 1]);
    float x = 0.f;
    for (int p = s; p < e; p++)
        x += __ldg(&g_msg[(size_t)p * NC + lane]);
    x *= g_deg[n];

    float h = out[(size_t)n * OUTC + (size_t)(t - 1) * NC + lane];

    float ir = bi[lane], iz = bi[32 + lane], in_ = bi[64 + lane];
    float hr = bh[lane], hz = bh[32 + lane], hn  = bh[64 + lane];
#pragma unroll
    for (int i = 0; i < NC; i++) {
        float xi = __shfl_sync(0xffffffffu, x, i);
        float hi = __shfl_sync(0xffffffffu, h, i);
        ir  = fmaf(xi, Wi[i * 96 + lane],      ir);
        iz  = fmaf(xi, Wi[i * 96 + 32 + lane], iz);
        in_ = fmaf(xi, Wi[i * 96 + 64 + lane], in_);
        hr  = fmaf(hi, Wh[i * 96 + lane],      hr);
        hz  = fmaf(hi, Wh[i * 96 + 32 + lane], hz);
        hn  = fmaf(hi, Wh[i * 96 + 64 + lane], hn);
    }
    float r  = 1.0f / (1.0f + expf(-(ir + hr)));
    float z  = 1.0f / (1.0f + expf(-(iz + hz)));
    float nn = tanhf(in_ + r * hn);
    float hv = (1.0f - z) * nn + z * h;
    out[(size_t)n * OUTC + (size_t)t * NC + lane] = hv;
    g_hxh[(size_t)n * NC + lane] = __float2half_rn(hv);
}

// ---------------------------------------------------------------------------
extern "C" void kernel_launch(void* const* d_in, const int* in_sizes, int n_in,
                              void* d_out, int out_size) {
    const float* hx  = (const float*)d_in[0];
    const int*   ei  = (const int*)d_in[1];
    const float* ef  = (const float*)d_in[2];
    const float* fW1 = (const float*)d_in[3];
    const float* fb1 = (const float*)d_in[4];
    const float* fW2 = (const float*)d_in[5];
    const float* fb2 = (const float*)d_in[6];
    const float* Wi  = (const float*)d_in[7];
    const float* Wh  = (const float*)d_in[8];
    const float* bi  = (const float*)d_in[9];
    const float* bh  = (const float*)d_in[10];
    float* out = (float*)d_out;

    const int N = in_sizes[0] / NC;   // 20000
    const int E = in_sizes[1] / 2;    // 200000
    const int* src = ei;
    const int* dst = ei + E;

    dim3 qgrid(MPAD / 64, 2048 / 128);

    prep0_kernel<<<(E * 32 + 255) / 256, 256>>>(ef, fW1, fb1, fW2, hx, out, N, E);
    count_kernel<<<(E + 255) / 256, 256>>>(src, dst, E);
    scan_kernel<<<1, 256>>>(N);
    qgemm_kernel<<<qgrid, 256>>>();                     // launch #4 (profiled)
    scatter_kernel<<<(E + 255) / 256, 256>>>(src, dst, N, E);

    for (int t = 1; t <= NREP; t++) {
        if (t > 1) qgemm_kernel<<<qgrid, 256>>>();
        msg_kernel<<<(N * 32 + 255) / 256, 256>>>(out, fb2, N, t);
        gru_kernel<<<(N * 32 + 255) / 256, 256>>>(out, Wi, Wh, bi, bh, N, t);
    }
}

// round 9
// speedup vs baseline: 1.0034x; 1.0034x over previous
#include <cuda_runtime.h>
#include <cuda_fp16.h>
#include <mma.h>
#include <math.h>

using namespace nvcuda;

#define NNODES 20000
#define NEDGES 200000
#define NC     32
#define FDIM   13
#define FHID   64
#define NREP   10
#define OUTC   (NC * (NREP + 1))   // 352
#define MPAD   20032               // NNODES padded to 64

// Scratch (__device__ globals; allocation-free rule). Zero-initialized at load.
__device__ __half g_Q[(size_t)MPAD * 2048];       // 82 MB per-node projections
__device__ __half g_h1[(size_t)NEDGES * FHID];    // 25.6 MB (edge order)
__device__ __half g_fW2pp[32 * 2048];             // permuted fW2: [i][o*64+k]
__device__ __half g_hxh[(size_t)MPAD * NC];       // fp16 copy of current hx
__device__ float  g_msg[(size_t)NEDGES * NC];     // 25.6 MB msgs, dst-sorted
__device__ float  g_deg[NNODES];
__device__ int    g_cnt[NNODES], g_cur[NNODES];   // src CSR build (zeroed by cleanup)
__device__ int    g_cntd[NNODES], g_curd[NNODES]; // dst CSR build (zeroed by cleanup)
__device__ int    g_off[NNODES + 1];              // src CSR offsets
__device__ int    g_offd[NNODES + 1];             // dst CSR offsets
__device__ int    g_perm[NEDGES];                 // src-sorted pos -> edge id
__device__ int    g_dpos[NEDGES];                 // src-sorted pos -> dst-sorted pos

typedef unsigned long long ull;

__device__ __forceinline__ float2 int_as_f2h(int v) {
    __half2 h; *(int*)&h = v; return __half22float2(h);
}
__device__ __forceinline__ ull pack2(float x, float y) {
    ull r; asm("mov.b64 %0, {%1, %2};" : "=l"(r) : "f"(x), "f"(y)); return r;
}
__device__ __forceinline__ ull fma2(ull a, ull b, ull c) {
    ull d; asm("fma.rn.f32x2 %0, %1, %2, %3;" : "=l"(d) : "l"(a), "l"(b), "l"(c)); return d;
}
__device__ __forceinline__ float sum2(ull v) {
    float x, y; asm("mov.b64 {%0, %1}, %2;" : "=f"(x), "=f"(y) : "l"(v)); return x + y;
}

// ---------------------------------------------------------------------------
// launch 1 — prep0: h1 (warp/edge) + DEGREE COUNTS (counters pre-zeroed) +
// copy0 + fW2 permute + hxh pad
// ---------------------------------------------------------------------------
__global__ void prep0_kernel(const float* __restrict__ ef,
                             const float* __restrict__ fW1,
                             const float* __restrict__ fb1,
                             const float* __restrict__ fW2,
                             const float* __restrict__ hx,
                             const int* __restrict__ src,
                             const int* __restrict__ dst,
                             float* __restrict__ out,
                             int N, int E) {
    int gtid = blockIdx.x * blockDim.x + threadIdx.x;
    int e    = gtid >> 5;
    int lane = gtid & 31;

    if (e < E) {
        float efv = (lane < FDIM) ? ef[(size_t)e * FDIM + lane] : 0.f;
        float a0 = fb1[lane], a1 = fb1[lane + 32];
#pragma unroll
        for (int j = 0; j < FDIM; j++) {
            float x = __shfl_sync(0xffffffffu, efv, j);
            a0 = fmaf(x, fW1[j * FHID + lane],      a0);
            a1 = fmaf(x, fW1[j * FHID + lane + 32], a1);
        }
        g_h1[(size_t)e * FHID + lane]      = __float2half_rn(fmaxf(a0, 0.f));
        g_h1[(size_t)e * FHID + lane + 32] = __float2half_rn(fmaxf(a1, 0.f));
    }
    if (gtid < E) {    // degree counting (g_cnt/g_cntd are zero at launch start)
        atomicAdd(&g_cnt[src[gtid]], 1);
        atomicAdd(&g_cntd[dst[gtid]], 1);
    }
    if (gtid < N * NC) {
        float v = hx[gtid];
        out[(size_t)(gtid >> 5) * OUTC + (gtid & 31)] = v;
        g_hxh[gtid] = __float2half_rn(v);
    }
    if (gtid < (MPAD - NNODES) * NC)
        g_hxh[(size_t)NNODES * NC + gtid] = __float2half_rn(0.f);
    if (gtid < 32 * 2048) {
        int i = gtid >> 11, rem = gtid & 2047, o = rem >> 6, k = rem & 63;
        g_fW2pp[gtid] = __float2half_rn(fW2[k * 1024 + i * 32 + o]);
    }
}

// ---------------------------------------------------------------------------
// launch 2 — qgemm (+ scan on first call, done by block (0,0)):
// Q = hxh @ fW2pp, WMMA, block tile 64(M) x 128(N), K=32.
// ---------------------------------------------------------------------------
#define QBS_LD 136

__global__ void qgemm_kernel(int N, int do_scan) {
    __shared__ __align__(16) __half Bs[32 * QBS_LD];
    __shared__ int part[256];

    const int m0 = blockIdx.x * 64;
    const int n0 = blockIdx.y * 128;
    const int tid = threadIdx.x;
    const int wid = tid >> 5;
    const int wm = wid & 3, wn = wid >> 2;

    // first call: block (0,0) runs the two exclusive scans before its GEMM work
    if (do_scan && blockIdx.x == 0 && blockIdx.y == 0) {
        int chunk = (N + 255) / 256;
        int lo = tid * chunk, hi = min(lo + chunk, N);
        int s = 0;
        for (int i = lo; i < hi; i++) s += g_cnt[i];
        part[tid] = s;
        __syncthreads();
        if (tid == 0) {
            int run = 0;
            for (int i = 0; i < 256; i++) { int v = part[i]; part[i] = run; run += v; }
            g_off[N] = run;
        }
        __syncthreads();
        int run = part[tid];
        for (int i = lo; i < hi; i++) { g_off[i] = run; run += g_cnt[i]; }
        __syncthreads();

        s = 0;
        for (int i = lo; i < hi; i++) s += g_cntd[i];
        part[tid] = s;
        __syncthreads();
        if (tid == 0) {
            int run2 = 0;
            for (int i = 0; i < 256; i++) { int v = part[i]; part[i] = run2; run2 += v; }
            g_offd[N] = run2;
        }
        __syncthreads();
        run = part[tid];
        for (int i = lo; i < hi; i++) { g_offd[i] = run; run += g_cntd[i]; }
        __syncthreads();
    }

#pragma unroll
    for (int i = tid; i < 512; i += 256) {
        int r = i >> 4, s = i & 15;
        *(int4*)(Bs + r * QBS_LD + s * 8) =
            *(const int4*)(g_fW2pp + (size_t)r * 2048 + n0 + s * 8);
    }
    __syncthreads();

    wmma::fragment<wmma::accumulator, 16, 16, 16, float> acc[4];
#pragma unroll
    for (int j = 0; j < 4; j++) wmma::fill_fragment(acc[j], 0.0f);

#pragma unroll
    for (int k = 0; k < 2; k++) {
        wmma::fragment<wmma::matrix_a, 16, 16, 16, __half, wmma::row_major> af;
        wmma::load_matrix_sync(af, g_hxh + (size_t)(m0 + wm * 16) * NC + k * 16, NC);
#pragma unroll
        for (int j = 0; j < 4; j++) {
            wmma::fragment<wmma::matrix_b, 16, 16, 16, __half, wmma::row_major> bf;
            wmma::load_matrix_sync(bf, Bs + (k * 16) * QBS_LD + wn * 64 + j * 16, QBS_LD);
            wmma::mma_sync(acc[j], af, bf, acc[j]);
        }
    }

#pragma unroll
    for (int j = 0; j < 4; j++) {
        wmma::fragment<wmma::accumulator, 16, 16, 16, __half> hc;
#pragma unroll
        for (int i = 0; i < hc.num_elements; i++)
            hc.x[i] = __float2half_rn(acc[j].x[i]);
        wmma::store_matrix_sync(g_Q + (size_t)(m0 + wm * 16) * 2048 + n0 + wn * 64 + j * 16,
                                hc, 2048, wmma::mem_row_major);
    }
}

// ---------------------------------------------------------------------------
// launch 3 — CSR scatter (both orders) + invdeg
// ---------------------------------------------------------------------------
__global__ void scatter_kernel(const int* __restrict__ src,
                               const int* __restrict__ dst, int N, int E) {
    int e = blockIdx.x * blockDim.x + threadIdx.x;
    if (e < E) {
        int s = src[e], d = dst[e];
        int ps = g_off[s]  + atomicAdd(&g_cur[s], 1);
        int pd = g_offd[d] + atomicAdd(&g_curd[d], 1);
        g_perm[ps] = e;
        g_dpos[ps] = pd;
    }
    if (e < N) g_deg[e] = 1.0f / fmaxf((float)g_cntd[e], 1.0f);
}

// ---------------------------------------------------------------------------
// launch 4 (PROFILED) — msg: warp per src node; LDS.128 broadcast of h1,
// f32x2 FMA with 4 chains, store to dst-sorted g_msg (no atomics).
// ---------------------------------------------------------------------------
#define MSG_WARPS 8
__global__ void msg_kernel(const float* __restrict__ out,
                           const float* __restrict__ fb2,
                           int N, int t) {
    __shared__ __align__(16) ull hbuf[MSG_WARPS][2][32];
    int n    = (blockIdx.x * blockDim.x + threadIdx.x) >> 5;
    int lane = threadIdx.x & 31;
    int w    = (threadIdx.x >> 5);
    if (n >= N) return;
    int start = __ldg(&g_off[n]), end = __ldg(&g_off[n + 1]);
    if (start == end) return;

    // Q row -> packed f32x2 registers (lane o owns k=0..63 -> 32 pairs)
    ull qf2[32];
    const int4* qp = (const int4*)(g_Q + (size_t)n * 2048 + lane * 64);
#pragma unroll
    for (int j = 0; j < 8; j++) {
        int4 v = __ldg(qp + j);
        const int* vi = (const int*)&v;
#pragma unroll
        for (int u = 0; u < 4; u++) {
            float2 f = int_as_f2h(vi[u]);
            qf2[j * 4 + u] = pack2(f.x, f.y);
        }
    }
    // bias: bn[o] = sum_i hx[n,i] * fb2[i*32+o]
    float hxl = out[(size_t)n * OUTC + (size_t)(t - 1) * NC + lane];
    float bn = 0.f;
#pragma unroll
    for (int i = 0; i < NC; i++)
        bn = fmaf(__shfl_sync(0xffffffffu, hxl, i), fb2[i * 32 + lane], bn);

    const int* h1i = (const int*)g_h1;

    // prefetch first edge
    int p = start;
    int e0 = __ldg(&g_perm[p]);
    int dp0 = __ldg(&g_dpos[p]);
    int hv0 = __ldg(h1i + (size_t)e0 * 32 + lane);

    while (p < end) {
        int hv = hv0, dp = dp0;
        int np = p + 1;
        if (np < end) {                        // prefetch next (overlaps compute)
            int e1 = __ldg(&g_perm[np]);
            dp0 = __ldg(&g_dpos[np]);
            hv0 = __ldg(h1i + (size_t)e1 * 32 + lane);
        }
        int buf = p & 1;
        ull* hb = &hbuf[w][buf][0];

        float2 hf = int_as_f2h(hv);
        hb[lane] = pack2(hf.x, hf.y);          // h[2*lane], h[2*lane+1]
        __syncwarp();

        const ulonglong2* hb2 = (const ulonglong2*)hb;  // LDS.128 broadcasts
        ull a0 = 0, a1 = 0, a2 = 0, a3 = 0;    // 4 independent chains
#pragma unroll
        for (int j = 0; j < 16; j += 4) {
            ulonglong2 p0 = hb2[j];
            ulonglong2 p1 = hb2[j + 1];
            ulonglong2 p2 = hb2[j + 2];
            ulonglong2 p3 = hb2[j + 3];
            a0 = fma2(p0.x, qf2[2 * j],     a0);
            a0 = fma2(p0.y, qf2[2 * j + 1], a0);
            a1 = fma2(p1.x, qf2[2 * j + 2], a1);
            a1 = fma2(p1.y, qf2[2 * j + 3], a1);
            a2 = fma2(p2.x, qf2[2 * j + 4], a2);
            a2 = fma2(p2.y, qf2[2 * j + 5], a2);
            a3 = fma2(p3.x, qf2[2 * j + 6], a3);
            a3 = fma2(p3.y, qf2[2 * j + 7], a3);
        }
        float m = (sum2(a0) + sum2(a1)) + (sum2(a2) + sum2(a3));
        g_msg[(size_t)dp * NC + lane] = m + bn;
        p = np;
    }
}

// ---------------------------------------------------------------------------
// GRU: warp per node. Segmented sum over dst-CSR msgs, then GRU math.
// ---------------------------------------------------------------------------
__global__ void gru_kernel(float* __restrict__ out,
                           const float* __restrict__ Wi,
                           const float* __restrict__ Wh,
                           const float* __restrict__ bi,
                           const float* __restrict__ bh,
                           int N, int t) {
    int n    = (blockIdx.x * blockDim.x + threadIdx.x) >> 5;
    int lane = threadIdx.x & 31;
    if (n >= N) return;

    int s = __ldg(&g_offd[n]), e = __ldg(&g_offd[n + 1]);
    float x = 0.f;
    for (int p = s; p < e; p++)
        x += __ldg(&g_msg[(size_t)p * NC + lane]);
    x *= g_deg[n];

    float h = out[(size_t)n * OUTC + (size_t)(t - 1) * NC + lane];

    float ir = bi[lane], iz = bi[32 + lane], in_ = bi[64 + lane];
    float hr = bh[lane], hz = bh[32 + lane], hn  = bh[64 + lane];
#pragma unroll
    for (int i = 0; i < NC; i++) {
        float xi = __shfl_sync(0xffffffffu, x, i);
        float hi = __shfl_sync(0xffffffffu, h, i);
        ir  = fmaf(xi, Wi[i * 96 + lane],      ir);
        iz  = fmaf(xi, Wi[i * 96 + 32 + lane], iz);
        in_ = fmaf(xi, Wi[i * 96 + 64 + lane], in_);
        hr  = fmaf(hi, Wh[i * 96 + lane],      hr);
        hz  = fmaf(hi, Wh[i * 96 + 32 + lane], hz);
        hn  = fmaf(hi, Wh[i * 96 + 64 + lane], hn);
    }
    float r  = 1.0f / (1.0f + expf(-(ir + hr)));
    float z  = 1.0f / (1.0f + expf(-(iz + hz)));
    float nn = tanhf(in_ + r * hn);
    float hv = (1.0f - z) * nn + z * h;
    out[(size_t)n * OUTC + (size_t)t * NC + lane] = hv;
    g_hxh[(size_t)n * NC + lane] = __float2half_rn(hv);
}

// tail — re-zero CSR counters so every graph replay starts from a clean state
__global__ void cleanup_kernel(int N) {
    int i = blockIdx.x * blockDim.x + threadIdx.x;
    if (i < N) { g_cnt[i] = 0; g_cntd[i] = 0; g_cur[i] = 0; g_curd[i] = 0; }
}

// ---------------------------------------------------------------------------
extern "C" void kernel_launch(void* const* d_in, const int* in_sizes, int n_in,
                              void* d_out, int out_size) {
    const float* hx  = (const float*)d_in[0];
    const int*   ei  = (const int*)d_in[1];
    const float* ef  = (const float*)d_in[2];
    const float* fW1 = (const float*)d_in[3];
    const float* fb1 = (const float*)d_in[4];
    const float* fW2 = (const float*)d_in[5];
    const float* fb2 = (const float*)d_in[6];
    const float* Wi  = (const float*)d_in[7];
    const float* Wh  = (const float*)d_in[8];
    const float* bi  = (const float*)d_in[9];
    const float* bh  = (const float*)d_in[10];
    float* out = (float*)d_out;

    const int N = in_sizes[0] / NC;   // 20000
    const int E = in_sizes[1] / 2;    // 200000
    const int* src = ei;
    const int* dst = ei + E;

    dim3 qgrid(MPAD / 64, 2048 / 128);

    prep0_kernel<<<(E * 32 + 255) / 256, 256>>>(ef, fW1, fb1, fW2, hx, src, dst, out, N, E);  // 1
    qgemm_kernel<<<qgrid, 256>>>(N, 1);                                                       // 2 (+scan)
    scatter_kernel<<<(E + 255) / 256, 256>>>(src, dst, N, E);                                 // 3

    for (int t = 1; t <= NREP; t++) {
        if (t > 1) qgemm_kernel<<<qgrid, 256>>>(N, 0);
        msg_kernel<<<(N * 32 + 255) / 256, 256>>>(out, fb2, N, t);   // t=1: launch #4 (profiled)
        gru_kernel<<<(N * 32 + 255) / 256, 256>>>(out, Wi, Wh, bi, bh, N, t);
    }
    cleanup_kernel<<<(N + 255) / 256, 256>>>(N);
}